// round 1
// baseline (speedup 1.0000x reference)
#include <cuda_runtime.h>
#include <cstdint>

// ---------------------------------------------------------------------------
// VectorBasis: out[a,m,o] = sum_{edges e with center a}
//     fc(d_e) * Y_m(e) * sum_n R_n(d_e) * T[sc_a, sn_e, n, o]
// where T[sc,sn,n,o] = sum_q W_alch[sn,q] * emb[sc, n*4+q] * Wc[o, n*4+q]
// (exact refactoring of reference: contraction pushed into the edge loop)
// ---------------------------------------------------------------------------

#define A_MAX 100000
// padded accumulator: 12 floats per atom (3 rows m of [h0,h1,h2,pad]) so each
// row is a 16B-aligned float4 -> one red.global.add.v4.f32 per m
__device__ float g_scratch[A_MAX * 12];

__device__ __forceinline__ void red_add_v4(float* p, float a, float b, float c, float d) {
    asm volatile("red.global.add.v4.f32 [%0], {%1, %2, %3, %4};"
                 :: "l"(p), "f"(a), "f"(b), "f"(c), "f"(d)
                 : "memory");
}

__global__ void __launch_bounds__(256)
edge_kernel(const float* __restrict__ vecs,     // (E,3)
            const int*   __restrict__ centers,  // (E,)
            const int*   __restrict__ neighbors,// (E,)
            const int*   __restrict__ species,  // (A,)
            const float* __restrict__ W_alch,   // (4,4)
            const float* __restrict__ emb,      // (4,32)
            const float* __restrict__ Wc,       // (3,32)
            float*       __restrict__ scratch,  // (A,12)
            int E)
{
    // Per-species-pair contraction table, padded stride 25 (gcd(25,32)=1 ->
    // no bank conflicts for lane-varying pair index).
    __shared__ float sT[16 * 25];
    for (int t = threadIdx.x; t < 16 * 24; t += blockDim.x) {
        int p = t / 24, r = t - p * 24;
        int n = r / 3,  o = r - n * 3;
        int sc = p >> 2, sn = p & 3;
        float v = 0.f;
#pragma unroll
        for (int q = 0; q < 4; q++) {
            int d = n * 4 + q;
            v = fmaf(W_alch[sn * 4 + q] * emb[sc * 32 + d], Wc[o * 32 + d], v);
        }
        sT[p * 25 + r] = v;
    }
    __syncthreads();

    int e = blockIdx.x * blockDim.x + threadIdx.x;
    if (e >= E) return;

    float vx = vecs[e * 3 + 0];
    float vy = vecs[e * 3 + 1];
    float vz = vecs[e * 3 + 2];

    float d2   = fmaf(vx, vx, fmaf(vy, vy, vz * vz)) + 1e-12f;
    float invd = rsqrtf(d2);
    float d    = d2 * invd;

    int a  = centers[e];
    int sc = species[a];
    int sn = species[neighbors[e]];
    const float* T = &sT[(sc * 4 + sn) * 25];

    // R_n = sin(n*pi*d/rc)/d via Chebyshev recurrence, invd folded into r1
    float th = 0.62831853071795864769f * d; // pi/5 * d
    float s, c;
    __sincosf(th, &s, &c);
    float twoc = 2.0f * c;
    float r_nm1 = 0.0f;
    float r_n   = s * invd;

    float h0 = 0.f, h1 = 0.f, h2 = 0.f;
#pragma unroll
    for (int n = 0; n < 8; n++) {
        h0 = fmaf(r_n, T[n * 3 + 0], h0);
        h1 = fmaf(r_n, T[n * 3 + 1], h1);
        h2 = fmaf(r_n, T[n * 3 + 2], h2);
        float r_np1 = fmaf(twoc, r_n, -r_nm1);
        r_nm1 = r_n;
        r_n   = r_np1;
    }

    // shifted-cosine cutoff (rc=5, width=0.5)
    float fc;
    if (d < 4.5f) {
        fc = 1.0f;
    } else if (d < 5.0f) {
        fc = 0.5f * (__cosf(6.28318530717958647692f * (d - 4.5f)) + 1.0f);
    } else {
        fc = 0.0f;
    }

    float f  = fc * invd;
    float y0 = vy * f;   // m order (-1,0,1) -> (y,z,x)/d
    float y1 = vz * f;
    float y2 = vx * f;

    float* base = scratch + (size_t)a * 12;
    red_add_v4(base + 0, y0 * h0, y0 * h1, y0 * h2, 0.0f);
    red_add_v4(base + 4, y1 * h0, y1 * h1, y1 * h2, 0.0f);
    red_add_v4(base + 8, y2 * h0, y2 * h1, y2 * h2, 0.0f);
}

__global__ void __launch_bounds__(256)
finalize_kernel(const float* __restrict__ scratch, float* __restrict__ out, int total)
{
    int i = blockIdx.x * blockDim.x + threadIdx.x;
    if (i >= total) return;
    int a = i / 9;
    int r = i - a * 9;
    int m = r / 3;
    int o = r - m * 3;
    out[i] = scratch[(size_t)a * 12 + m * 4 + o];
}

extern "C" void kernel_launch(void* const* d_in, const int* in_sizes, int n_in,
                              void* d_out, int out_size)
{
    const float* vecs      = (const float*)d_in[0];
    const int*   centers   = (const int*)  d_in[1];
    const int*   neighbors = (const int*)  d_in[2];
    const int*   species   = (const int*)  d_in[3];
    // d_in[4] = structures, d_in[5] = atom_index_in_structure: unused by reference
    const float* W_alch    = (const float*)d_in[6];
    const float* emb       = (const float*)d_in[7];
    const float* Wc        = (const float*)d_in[8];

    int E = in_sizes[1];   // centers element count
    int A = in_sizes[3];   // species element count

    float* scratch = nullptr;
    cudaGetSymbolAddress((void**)&scratch, g_scratch);

    cudaMemsetAsync(scratch, 0, (size_t)A * 12 * sizeof(float), 0);

    int blocks = (E + 255) / 256;
    edge_kernel<<<blocks, 256>>>(vecs, centers, neighbors, species,
                                 W_alch, emb, Wc, scratch, E);

    int total = A * 9;
    finalize_kernel<<<(total + 255) / 256, 256>>>(scratch, (float*)d_out, total);
}